// round 9
// baseline (speedup 1.0000x reference)
#include <cuda_runtime.h>
#include <cstdint>

// LinearKAN: out[b,o] = sum_i w[i,o]*silu(x[b,i]) + sum_{i,k} T_k(clip(tanh(x[b,i])))*c[i,o,k]*w[i,o]
// == GEMM (64 x 4608) @ (4608 x 512), split-K over i, single fused kernel.
// Packing: f32x2 across adjacent o (no register repacking needed);
// basis stored duplicated [v,v] in smem so both FMA operands come straight from LDS.

#define BATCH   64
#define INF     512
#define OUTF    512
#define BASIS   8

#define NSPLIT  64              // K-splits over i
#define ISPLIT  (INF / NSPLIT)  // 8 i's per block
#define ISTAGE  4               // i's staged in smem at a time
#define NSTAGE  (ISPLIT / ISTAGE)  // 2
#define OTILE   64              // grid.x = 8
#define NCOL    (OUTF / OTILE)

#define SBDS    1160            // basis dup: 9*128 + 8 pad (floats per li)
#define SCWS    584             // cw:        9*64  + 8 pad (floats per li)

__device__ float g_partial[NSPLIT * BATCH * OUTF];   // 8 MB scratch
__device__ int   g_ctr[NCOL];                        // zero-init; self-resetting

__device__ __forceinline__ void fma2(unsigned long long &acc, unsigned long long a,
                                     unsigned long long b) {
    asm("fma.rn.f32x2 %0, %1, %2, %3;" : "=l"(acc) : "l"(a), "l"(b), "l"(acc));
}

__global__ __launch_bounds__(256, 4)
void kan_fused(const float* __restrict__ x,
               const float* __restrict__ w,
               const float* __restrict__ c,
               float* __restrict__ out) {
    __shared__ __align__(16) float sbd[ISTAGE * SBDS];   // basis dup [li][j][2b]
    __shared__ __align__(16) float scw[ISTAGE * SCWS];   // c*w       [li][j][o]
    __shared__ int s_last;

    const int tid  = threadIdx.x;
    const int o0   = blockIdx.x * OTILE;
    const int i0   = blockIdx.y * ISPLIT;

    // mainloop mapping: 4 o x 4 b per thread
    const int ogrp = tid & 15;               // o-quad index (16 quads = 64 o)
    const int bgrp = tid >> 4;               // 16 b-groups of 4 b
    const int oa   = 4 * ogrp;               // o offset within tile
    const int b0   = 4 * bgrp;

    // builder A (basis): one (li, b) per thread
    const int liA = tid & 3;
    const int bA  = tid >> 2;
    // builder B (cw): one (li, o) per thread
    const int liB = tid >> 6;
    const int oB  = tid & 63;

    // ---- prefetch stage 0 operands ----
    float xr = x[bA * INF + i0 + liA];
    float wr = w[(size_t)(i0 + liB) * OUTF + o0 + oB];
    float4 q0, q1;
    {
        const float4* cp = reinterpret_cast<const float4*>(
            c + ((size_t)(i0 + liB) * OUTF + o0 + oB) * BASIS);
        q0 = cp[0]; q1 = cp[1];
    }

    unsigned long long acc[2][4];            // [o-pair][b]
#pragma unroll
    for (int u = 0; u < 2; u++)
#pragma unroll
        for (int v = 0; v < 4; v++) acc[u][v] = 0ull;

    for (int stage = 0; stage < NSTAGE; stage++) {
        __syncthreads();   // previous mainloop readers done

        // ---- build basis slab (duplicated pairs) ----
        {
            float sil = xr / (1.0f + __expf(-xr));
            float t   = tanhf(xr);
            t = fminf(fmaxf(t, -1.0f + 1e-6f), 1.0f - 1e-6f);
            float2* sp = reinterpret_cast<float2*>(sbd + liA * SBDS + 2 * bA);
            sp[0]       = make_float2(sil, sil);
            float tm2 = t;                      // T1
            sp[64]      = make_float2(tm2, tm2);
            float tm1 = 2.0f * t * t - 1.0f;    // T2
            sp[128]     = make_float2(tm1, tm1);
#pragma unroll
            for (int k = 3; k <= BASIS; k++) {
                float tk = 2.0f * t * tm1 - tm2;
                sp[64 * k] = make_float2(tk, tk);
                tm2 = tm1; tm1 = tk;
            }
        }
        // ---- build cw slab ----
        {
            float* cwp = scw + liB * SCWS + oB;
            cwp[0]   = wr;
            cwp[64]  = q0.x * wr; cwp[128] = q0.y * wr;
            cwp[192] = q0.z * wr; cwp[256] = q0.w * wr;
            cwp[320] = q1.x * wr; cwp[384] = q1.y * wr;
            cwp[448] = q1.z * wr; cwp[512] = q1.w * wr;
        }
        __syncthreads();

        // ---- prefetch next stage (hidden under FMA mainloop) ----
        if (stage + 1 < NSTAGE) {
            const int ib = i0 + (stage + 1) * ISTAGE;
            xr = x[bA * INF + ib + liA];
            wr = w[(size_t)(ib + liB) * OUTF + o0 + oB];
            const float4* cp = reinterpret_cast<const float4*>(
                c + ((size_t)(ib + liB) * OUTF + o0 + oB) * BASIS);
            q0 = cp[0]; q1 = cp[1];
        }

        // ---- FMA mainloop ----
#pragma unroll
        for (int li = 0; li < ISTAGE; li++) {
            const float* cwp = scw + li * SCWS + oa;
            const float* sp  = sbd + li * SBDS + 2 * b0;
#pragma unroll
            for (int j = 0; j < 9; j++) {
                // cw quad: (cw[oa..oa+3]) -> two packed 64-bit operands, no movs
                ulonglong2 cq = *reinterpret_cast<const ulonglong2*>(cwp + j * 64);
                // basis dup: [v,v] broadcast loads (uniform address per half-warp)
                unsigned long long d0 = *reinterpret_cast<const unsigned long long*>(sp + j * 128 + 0);
                unsigned long long d1 = *reinterpret_cast<const unsigned long long*>(sp + j * 128 + 2);
                unsigned long long d2 = *reinterpret_cast<const unsigned long long*>(sp + j * 128 + 4);
                unsigned long long d3 = *reinterpret_cast<const unsigned long long*>(sp + j * 128 + 6);
                fma2(acc[0][0], cq.x, d0);
                fma2(acc[0][1], cq.x, d1);
                fma2(acc[0][2], cq.x, d2);
                fma2(acc[0][3], cq.x, d3);
                fma2(acc[1][0], cq.y, d0);
                fma2(acc[1][1], cq.y, d1);
                fma2(acc[1][2], cq.y, d2);
                fma2(acc[1][3], cq.y, d3);
            }
        }
    }

    // ---- write partials: g_partial[split][b][o], packed o-pairs -> STG.64 ----
    float* pp = g_partial + (size_t)blockIdx.y * (BATCH * OUTF);
#pragma unroll
    for (int v = 0; v < 4; v++) {
        const int b = b0 + v;
#pragma unroll
        for (int oo = 0; oo < 2; oo++)
            *reinterpret_cast<unsigned long long*>(pp + (size_t)b * OUTF + o0 + oa + 2 * oo) =
                acc[oo][v];
    }

    // ---- fused reduce: last block in this o-column sums the splits ----
    __threadfence();
    if (tid == 0)
        s_last = (atomicAdd(&g_ctr[blockIdx.x], 1) == NSPLIT - 1) ? 1 : 0;
    __syncthreads();
    if (s_last) {
        __threadfence();
        // 64 o x 64 b outputs = 1024 float4, 256 threads -> 4 quads each
#pragma unroll
        for (int rep = 0; rep < 4; rep++) {
            const int q  = tid + rep * 256;
            const int b  = q >> 4;
            const int oq = q & 15;
            const float* base = g_partial + (size_t)b * OUTF + o0 + oq * 4;
            float4 s = make_float4(0.f, 0.f, 0.f, 0.f);
#pragma unroll 8
            for (int sp2 = 0; sp2 < NSPLIT; sp2++) {
                float4 v = *reinterpret_cast<const float4*>(base + (size_t)sp2 * (BATCH * OUTF));
                s.x += v.x; s.y += v.y; s.z += v.z; s.w += v.w;
            }
            *reinterpret_cast<float4*>(out + (size_t)b * OUTF + o0 + oq * 4) = s;
        }
        __syncthreads();
        if (tid == 0) g_ctr[blockIdx.x] = 0;   // reset for next graph replay
    }
}

extern "C" void kernel_launch(void* const* d_in, const int* in_sizes, int n_in,
                              void* d_out, int out_size) {
    const float* x = (const float*)d_in[0];
    const float* w = (const float*)d_in[1];
    const float* c = (const float*)d_in[2];
    float* out = (float*)d_out;

    dim3 grid(NCOL, NSPLIT);   // (8, 64) = 512 blocks
    kan_fused<<<grid, 256>>>(x, w, c, out);
}

// round 10
// speedup vs baseline: 1.2449x; 1.2449x over previous
#include <cuda_runtime.h>
#include <cstdint>

// LinearKAN: out[b,o] = sum_i w[i,o]*silu(x[b,i]) + sum_{i,k} T_k(clip(tanh(x[b,i])))*c[i,o,k]*w[i,o]
// == GEMM (64 x 4608) @ (4608 x 512), split-K over i, single fused kernel.
// All global operands for ALL stages prefetched at block start (MLP>=8);
// f32x2 packing across adjacent o; basis duplicated [v,v] in smem -> zero-MOV FMA loop.

#define BATCH   64
#define INF     512
#define OUTF    512
#define BASIS   8

#define NSPLIT  32              // K-splits over i
#define ISPLIT  (INF / NSPLIT)  // 16 i's per block
#define ISTAGE  4               // i's staged in smem at a time
#define NSTAGE  (ISPLIT / ISTAGE)  // 4
#define OTILE   64              // grid.x = 8
#define NCOL    (OUTF / OTILE)

#define SBDS    1160            // basis dup: 9*128 + 8 pad (floats per li)
#define SCWS    584             // cw:        9*64  + 8 pad (floats per li)

__device__ float g_partial[NSPLIT * BATCH * OUTF];   // 4 MB scratch
__device__ int   g_ctr[NCOL];                        // zero-init; self-resetting

__device__ __forceinline__ void fma2(unsigned long long &acc, unsigned long long a,
                                     unsigned long long b) {
    asm("fma.rn.f32x2 %0, %1, %2, %3;" : "=l"(acc) : "l"(a), "l"(b), "l"(acc));
}

__global__ __launch_bounds__(256, 2)
void kan_fused(const float* __restrict__ x,
               const float* __restrict__ w,
               const float* __restrict__ c,
               float* __restrict__ out) {
    __shared__ __align__(16) float sbd[ISTAGE * SBDS];   // basis dup [li][j][2b]
    __shared__ __align__(16) float scw[ISTAGE * SCWS];   // c*w       [li][j][o]
    __shared__ int s_last;

    const int tid  = threadIdx.x;
    const int o0   = blockIdx.x * OTILE;
    const int i0   = blockIdx.y * ISPLIT;

    // mainloop mapping: 4 o x 4 b per thread
    const int ogrp = tid & 15;               // o-quad index (16 quads = 64 o)
    const int bgrp = tid >> 4;               // 16 b-groups of 4 b
    const int oa   = 4 * ogrp;
    const int b0   = 4 * bgrp;

    // builder A (basis): one (li, b) per thread
    const int liA = tid & 3;
    const int bA  = tid >> 2;
    // builder B (cw): one (li, o) per thread
    const int liB = tid >> 6;
    const int oB  = tid & 63;

    // ---- prefetch ALL stages' operands at block start (MLP >= 8) ----
    float  xr[NSTAGE], wr[NSTAGE];
    float4 q0[NSTAGE], q1[NSTAGE];
#pragma unroll
    for (int s = 0; s < NSTAGE; s++) {
        const int ib = i0 + s * ISTAGE;
        xr[s] = x[bA * INF + ib + liA];
        wr[s] = w[(size_t)(ib + liB) * OUTF + o0 + oB];
        const float4* cp = reinterpret_cast<const float4*>(
            c + ((size_t)(ib + liB) * OUTF + o0 + oB) * BASIS);
        q0[s] = cp[0];
        q1[s] = cp[1];
    }

    unsigned long long acc[2][4];            // [o-pair][b]
#pragma unroll
    for (int u = 0; u < 2; u++)
#pragma unroll
        for (int v = 0; v < 4; v++) acc[u][v] = 0ull;

#pragma unroll
    for (int stage = 0; stage < NSTAGE; stage++) {
        __syncthreads();   // previous mainloop readers done

        // ---- build basis slab (duplicated pairs) ----
        {
            float xv  = xr[stage];
            float sil = xv / (1.0f + __expf(-xv));
            float t   = tanhf(xv);
            t = fminf(fmaxf(t, -1.0f + 1e-6f), 1.0f - 1e-6f);
            float2* sp = reinterpret_cast<float2*>(sbd + liA * SBDS + 2 * bA);
            sp[0]       = make_float2(sil, sil);
            float tm2 = t;                      // T1
            sp[64]      = make_float2(tm2, tm2);
            float tm1 = 2.0f * t * t - 1.0f;    // T2
            sp[128]     = make_float2(tm1, tm1);
#pragma unroll
            for (int k = 3; k <= BASIS; k++) {
                float tk = 2.0f * t * tm1 - tm2;
                sp[64 * k] = make_float2(tk, tk);
                tm2 = tm1; tm1 = tk;
            }
        }
        // ---- build cw slab ----
        {
            float wv = wr[stage];
            float* cwp = scw + liB * SCWS + oB;
            cwp[0]   = wv;
            cwp[64]  = q0[stage].x * wv; cwp[128] = q0[stage].y * wv;
            cwp[192] = q0[stage].z * wv; cwp[256] = q0[stage].w * wv;
            cwp[320] = q1[stage].x * wv; cwp[384] = q1[stage].y * wv;
            cwp[448] = q1[stage].z * wv; cwp[512] = q1[stage].w * wv;
        }
        __syncthreads();

        // ---- FMA mainloop ----
#pragma unroll
        for (int li = 0; li < ISTAGE; li++) {
            const float* cwp = scw + li * SCWS + oa;
            const float* sp  = sbd + li * SBDS + 2 * b0;
#pragma unroll
            for (int j = 0; j < 9; j++) {
                // cw quad (4 adjacent o) -> two packed 64-bit operands, no movs
                ulonglong2 cq = *reinterpret_cast<const ulonglong2*>(cwp + j * 64);
                // basis dup [v,v] -> direct 64-bit operands, broadcast-friendly
                unsigned long long d0 = *reinterpret_cast<const unsigned long long*>(sp + j * 128 + 0);
                unsigned long long d1 = *reinterpret_cast<const unsigned long long*>(sp + j * 128 + 2);
                unsigned long long d2 = *reinterpret_cast<const unsigned long long*>(sp + j * 128 + 4);
                unsigned long long d3 = *reinterpret_cast<const unsigned long long*>(sp + j * 128 + 6);
                fma2(acc[0][0], cq.x, d0);
                fma2(acc[0][1], cq.x, d1);
                fma2(acc[0][2], cq.x, d2);
                fma2(acc[0][3], cq.x, d3);
                fma2(acc[1][0], cq.y, d0);
                fma2(acc[1][1], cq.y, d1);
                fma2(acc[1][2], cq.y, d2);
                fma2(acc[1][3], cq.y, d3);
            }
        }
    }

    // ---- write partials: g_partial[split][b][o], packed o-pairs -> STG.64 ----
    float* pp = g_partial + (size_t)blockIdx.y * (BATCH * OUTF);
#pragma unroll
    for (int v = 0; v < 4; v++) {
        const int b = b0 + v;
#pragma unroll
        for (int oo = 0; oo < 2; oo++)
            *reinterpret_cast<unsigned long long*>(pp + (size_t)b * OUTF + o0 + oa + 2 * oo) =
                acc[oo][v];
    }

    // ---- fused reduce: last block in this o-column sums the splits ----
    __threadfence();
    if (tid == 0)
        s_last = (atomicAdd(&g_ctr[blockIdx.x], 1) == NSPLIT - 1) ? 1 : 0;
    __syncthreads();
    if (s_last) {
        __threadfence();
        // 64 o x 64 b outputs = 1024 float4, 256 threads -> 4 quads each
#pragma unroll
        for (int rep = 0; rep < 4; rep++) {
            const int q  = tid + rep * 256;
            const int b  = q >> 4;
            const int oq = q & 15;
            const float* base = g_partial + (size_t)b * OUTF + o0 + oq * 4;
            float4 s = make_float4(0.f, 0.f, 0.f, 0.f);
#pragma unroll 8
            for (int sp2 = 0; sp2 < NSPLIT; sp2++) {
                float4 v = *reinterpret_cast<const float4*>(base + (size_t)sp2 * (BATCH * OUTF));
                s.x += v.x; s.y += v.y; s.z += v.z; s.w += v.w;
            }
            *reinterpret_cast<float4*>(out + (size_t)b * OUTF + o0 + oq * 4) = s;
        }
        __syncthreads();
        if (tid == 0) g_ctr[blockIdx.x] = 0;   // reset for next graph replay
    }
}

extern "C" void kernel_launch(void* const* d_in, const int* in_sizes, int n_in,
                              void* d_out, int out_size) {
    const float* x = (const float*)d_in[0];
    const float* w = (const float*)d_in[1];
    const float* c = (const float*)d_in[2];
    float* out = (float*)d_out;

    dim3 grid(NCOL, NSPLIT);   // (8, 32) = 256 blocks
    kan_fused<<<grid, 256>>>(x, w, c, out);
}

// round 12
// speedup vs baseline: 1.4165x; 1.1379x over previous
#include <cuda_runtime.h>
#include <cuda_bf16.h>
#include <cstdint>

// LinearKAN via warp-level bf16 mma.sync (m16n8k16) with hi/lo compensation.
//   out[b,o] = sum_{j,i} basis_j(x[b,i]) * W2[(j,i),o]
//   basis_0 = silu(x), basis_j = T_j(clip(tanh(x)));  W2[(j,i),o] = j==0 ? w[i,o] : c[i,o,j-1]*w[i,o]
// Grid (8 o-tiles x 16 i-splits): each (i,o) pair belongs to exactly ONE CTA, so
// B = W2^T is built in-kernel (c read exactly once, no prep pass).
// A,B stored as bf16 hi+lo; D = Ah*Bh + Ah*Bl + Al*Bh in f32 accum (drop lo*lo).

#define BATCH 64
#define INF   512
#define OUTF  512
#define BASIS 8

#define NSPLIT 16
#define ISPL   (INF / NSPLIT)      // 32 i's per CTA
#define NO     64                  // o's per CTA
#define NCOL   (OUTF / NO)         // 8
#define KB     (9 * ISPL)          // 288 k per CTA (9 j-groups x 32 i)
#define NK16   (KB / 16)           // 18 k16 steps per pass

// smem pitches (bytes): chosen for 16B-aligned, bank-conflict-free ldmatrix
#define APIT 592                   // A row pitch: 64 rows x 576B data (+16 pad); stride 148 words -> 20 banks
#define BPIT 144                   // B row pitch: 288 rows x 128B data (+16 pad); stride 36 words -> 4 banks

#define SM_AHI 0
#define SM_ALO (SM_AHI + 64 * APIT)            // 37888
#define SM_BHI (SM_ALO + 64 * APIT)            // 75776
#define SM_BLO (SM_BHI + KB * BPIT)            // 117248
#define SM_TOT (SM_BLO + KB * BPIT)            // 158720

__device__ float g_partial[NSPLIT * BATCH * OUTF];   // 2 MB
__device__ int   g_ctr[NCOL];                        // zero-init; self-resetting

// ---------------- helpers ----------------
__device__ __forceinline__ uint32_t smem_u32(const void* p) {
    uint32_t a;
    asm("{ .reg .u64 t; cvta.to.shared.u64 t, %1; cvt.u32.u64 %0, t; }" : "=r"(a) : "l"(p));
    return a;
}
// split (v0,v1) into packed bf16x2 hi and lo (lo = v - bf16(v))
__device__ __forceinline__ void hilo2(float v0, float v1, uint32_t& hi, uint32_t& lo) {
    asm("cvt.rn.bf16x2.f32 %0, %1, %2;" : "=r"(hi) : "f"(v1), "f"(v0));  // low16 = v0
    float h0 = __uint_as_float(hi << 16);
    float h1 = __uint_as_float(hi & 0xffff0000u);
    float l0 = v0 - h0, l1 = v1 - h1;
    asm("cvt.rn.bf16x2.f32 %0, %1, %2;" : "=r"(lo) : "f"(l1), "f"(l0));
}
__device__ __forceinline__ void ldmA(uint32_t* a, uint32_t addr) {    // 16x16 A, row-major
    asm volatile("ldmatrix.sync.aligned.m8n8.x4.shared.b16 {%0,%1,%2,%3}, [%4];"
                 : "=r"(a[0]), "=r"(a[1]), "=r"(a[2]), "=r"(a[3]) : "r"(addr));
}
__device__ __forceinline__ void ldmB(uint32_t* b, uint32_t addr) {    // 16k x 8n B, [k][n] -> trans
    asm volatile("ldmatrix.sync.aligned.m8n8.x2.trans.shared.b16 {%0,%1}, [%2];"
                 : "=r"(b[0]), "=r"(b[1]) : "r"(addr));
}
__device__ __forceinline__ void mma16816(float* d, const uint32_t* a, const uint32_t* b) {
    asm volatile("mma.sync.aligned.m16n8k16.row.col.f32.bf16.bf16.f32 "
                 "{%0,%1,%2,%3}, {%4,%5,%6,%7}, {%8,%9}, {%0,%1,%2,%3};"
                 : "+f"(d[0]), "+f"(d[1]), "+f"(d[2]), "+f"(d[3])
                 : "r"(a[0]), "r"(a[1]), "r"(a[2]), "r"(a[3]), "r"(b[0]), "r"(b[1]));
}

__global__ __launch_bounds__(128, 1)
void kan_mma(const float* __restrict__ x,
             const float* __restrict__ w,
             const float* __restrict__ c,
             float* __restrict__ out) {
    extern __shared__ char sm[];
    __shared__ int s_last;

    const int tid  = threadIdx.x;
    const int wid  = tid >> 5, lane = tid & 31;
    const int o0   = blockIdx.x * NO;
    const int ks   = blockIdx.y;
    const int i0   = ks * ISPL;

    // ================= build A: basis hi/lo, [b][k] rows, k = j*32 + i =================
    // 512 tasks: (b, i-quad); per task all 9 j via Chebyshev recurrence in registers.
#pragma unroll
    for (int r = 0; r < 4; r++) {
        const int tau = tid + r * 128;
        const int b   = tau >> 3;
        const int iq  = (tau & 7) * 4;
        float4 xv = *reinterpret_cast<const float4*>(&x[(size_t)b * INF + i0 + iq]);
        float v[4] = {xv.x, xv.y, xv.z, xv.w};
        float sil[4], t[4], tm1[4], tm2[4];
#pragma unroll
        for (int u = 0; u < 4; u++) {
            sil[u] = v[u] / (1.0f + __expf(-v[u]));
            float tt = tanhf(v[u]);
            t[u] = fminf(fmaxf(tt, -1.0f + 1e-6f), 1.0f - 1e-6f);
        }
        const int rowoff = b * APIT + iq * 2;
        auto stA = [&](int j, const float* q) {
            uint32_t h01, l01, h23, l23;
            hilo2(q[0], q[1], h01, l01);
            hilo2(q[2], q[3], h23, l23);
            const int off = rowoff + j * (ISPL * 2);
            *reinterpret_cast<uint2*>(sm + SM_AHI + off) = make_uint2(h01, h23);
            *reinterpret_cast<uint2*>(sm + SM_ALO + off) = make_uint2(l01, l23);
        };
        stA(0, sil);
        stA(1, t);
#pragma unroll
        for (int u = 0; u < 4; u++) { tm2[u] = t[u]; tm1[u] = 2.0f * t[u] * t[u] - 1.0f; }
        stA(2, tm1);
#pragma unroll
        for (int k = 3; k <= BASIS; k++) {
            float tk[4];
#pragma unroll
            for (int u = 0; u < 4; u++) {
                tk[u] = 2.0f * t[u] * tm1[u] - tm2[u];
                tm2[u] = tm1[u]; tm1[u] = tk[u];
            }
            stA(k, tk);
        }
    }

    // ================= build B: W2^T hi/lo, [k][o] rows =================
    // j=0 rows (k = 0..31): plain w
#pragma unroll
    for (int r = 0; r < 4; r++) {
        const int tau = tid + r * 128;                 // 512 tasks: (i, o-quad)
        const int iL  = tau >> 4;
        const int oq  = (tau & 15) * 4;
        float4 wq = *reinterpret_cast<const float4*>(&w[(size_t)(i0 + iL) * OUTF + o0 + oq]);
        uint32_t h01, l01, h23, l23;
        hilo2(wq.x, wq.y, h01, l01);
        hilo2(wq.z, wq.w, h23, l23);
        const int off = iL * BPIT + oq * 2;
        *reinterpret_cast<uint2*>(sm + SM_BHI + off) = make_uint2(h01, h23);
        *reinterpret_cast<uint2*>(sm + SM_BLO + off) = make_uint2(l01, l23);
    }
    // j=1..8 rows: c*w.  1024 tasks: (h half, i, o-quad); c float4 covers 4 j's.
#pragma unroll
    for (int r = 0; r < 8; r++) {
        const int tau = tid + r * 128;
        const int h   = tau >> 9;
        const int rem = tau & 511;
        const int iL  = rem >> 4;
        const int oq  = (rem & 15) * 4;
        float4 wq = *reinterpret_cast<const float4*>(&w[(size_t)(i0 + iL) * OUTF + o0 + oq]);
        const float* wv = &wq.x;
        float4 cq[4];
#pragma unroll
        for (int u = 0; u < 4; u++)
            cq[u] = reinterpret_cast<const float4*>(c)
                        [((size_t)(i0 + iL) * OUTF + o0 + oq + u) * 2 + h];
        const float* cf[4] = {&cq[0].x, &cq[1].x, &cq[2].x, &cq[3].x};
#pragma unroll
        for (int jj = 0; jj < 4; jj++) {
            const int j = h * 4 + jj + 1;              // basis index 1..8
            float p0 = cf[0][jj] * wv[0], p1 = cf[1][jj] * wv[1];
            float p2 = cf[2][jj] * wv[2], p3 = cf[3][jj] * wv[3];
            uint32_t h01, l01, h23, l23;
            hilo2(p0, p1, h01, l01);
            hilo2(p2, p3, h23, l23);
            const int off = (j * ISPL + iL) * BPIT + oq * 2;
            *reinterpret_cast<uint2*>(sm + SM_BHI + off) = make_uint2(h01, h23);
            *reinterpret_cast<uint2*>(sm + SM_BLO + off) = make_uint2(l01, l23);
        }
    }
    __syncthreads();

    // ================= MMA mainloop =================
    const int n0 = wid * 16;                           // each warp: 16 o columns
    // per-lane ldmatrix bases
    const uint32_t aRow = (lane & 15), aSeg = (lane >> 4) * 16;
    const uint32_t aHiB = smem_u32(sm + SM_AHI) + aRow * APIT + aSeg;
    const uint32_t aLoB = smem_u32(sm + SM_ALO) + aRow * APIT + aSeg;
    const uint32_t bHiB = smem_u32(sm + SM_BHI) + (lane & 15) * BPIT + n0 * 2;
    const uint32_t bLoB = smem_u32(sm + SM_BLO) + (lane & 15) * BPIT + n0 * 2;

    float acc[4][2][4];
#pragma unroll
    for (int mt = 0; mt < 4; mt++)
#pragma unroll
        for (int nt = 0; nt < 2; nt++)
#pragma unroll
            for (int q = 0; q < 4; q++) acc[mt][nt][q] = 0.0f;

#pragma unroll
    for (int p = 0; p < 3; p++) {
        const uint32_t aB = (p < 2) ? aHiB : aLoB;     // passes: Ah*Bh, Ah*Bl, Al*Bh
        const uint32_t bB = (p == 1) ? bLoB : bHiB;
#pragma unroll 3
        for (int s = 0; s < NK16; s++) {
            uint32_t afr[4][4];
#pragma unroll
            for (int mt = 0; mt < 4; mt++)
                ldmA(afr[mt], aB + mt * 16 * APIT + s * 32);
            uint32_t bfr[2][2];
#pragma unroll
            for (int nt = 0; nt < 2; nt++)
                ldmB(bfr[nt], bB + s * 16 * BPIT + nt * 16);
#pragma unroll
            for (int mt = 0; mt < 4; mt++)
#pragma unroll
                for (int nt = 0; nt < 2; nt++)
                    mma16816(acc[mt][nt], afr[mt], bfr[nt]);
        }
    }

    // ================= write partials =================
    float* pp = g_partial + (size_t)ks * (BATCH * OUTF);
#pragma unroll
    for (int mt = 0; mt < 4; mt++)
#pragma unroll
        for (int nt = 0; nt < 2; nt++) {
            const int row = mt * 16 + (lane >> 2);
            const int col = o0 + n0 + nt * 8 + (lane & 3) * 2;
            *reinterpret_cast<float2*>(pp + (size_t)row * OUTF + col) =
                make_float2(acc[mt][nt][0], acc[mt][nt][1]);
            *reinterpret_cast<float2*>(pp + (size_t)(row + 8) * OUTF + col) =
                make_float2(acc[mt][nt][2], acc[mt][nt][3]);
        }

    // ================= fused reduce: last CTA per o-column =================
    __threadfence();
    if (tid == 0)
        s_last = (atomicAdd(&g_ctr[blockIdx.x], 1) == NSPLIT - 1) ? 1 : 0;
    __syncthreads();
    if (s_last) {
        __threadfence();
        // 64 b x 64 o = 1024 float4; 128 threads -> 8 each
#pragma unroll
        for (int rep = 0; rep < 8; rep++) {
            const int qi = tid + rep * 128;
            const int b  = qi >> 4;
            const int oq = qi & 15;
            const float* base = g_partial + (size_t)b * OUTF + o0 + oq * 4;
            float4 s = make_float4(0.f, 0.f, 0.f, 0.f);
#pragma unroll
            for (int sp = 0; sp < NSPLIT; sp++) {
                float4 v = *reinterpret_cast<const float4*>(base + (size_t)sp * (BATCH * OUTF));
                s.x += v.x; s.y += v.y; s.z += v.z; s.w += v.w;
            }
            *reinterpret_cast<float4*>(out + (size_t)b * OUTF + o0 + oq * 4) = s;
        }
        __syncthreads();
        if (tid == 0) g_ctr[blockIdx.x] = 0;           // reset for graph replay
    }
}

extern "C" void kernel_launch(void* const* d_in, const int* in_sizes, int n_in,
                              void* d_out, int out_size) {
    const float* x = (const float*)d_in[0];
    const float* w = (const float*)d_in[1];
    const float* c = (const float*)d_in[2];
    float* out = (float*)d_out;

    cudaFuncSetAttribute(kan_mma, cudaFuncAttributeMaxDynamicSharedMemorySize, SM_TOT);
    kan_mma<<<dim3(NCOL, NSPLIT), 128, SM_TOT>>>(x, w, c, out);
}

// round 14
// speedup vs baseline: 1.8243x; 1.2879x over previous
#include <cuda_runtime.h>
#include <cuda_bf16.h>
#include <cstdint>

// LinearKAN via warp-level bf16 mma.sync (m16n8k16) with hi/lo compensation.
//   out[b,o] = sum_{j,i} basis_j(x[b,i]) * W2[(j,i),o]
//   basis_0 = silu(x), basis_j = T_j(clip(tanh(x)));  W2[(j,i),o] = j==0 ? w[i,o] : c[i,o,j-1]*w[i,o]
// Grid (8 o-tiles x 16 i-splits) x 256 threads (8 warps). Each (i,o) pair belongs to
// exactly ONE CTA, so B = W2^T is built in-kernel (c read exactly once).
// A,B stored as bf16 hi+lo; D = Ah*Bh + Ah*Bl + Al*Bh in f32 accum (drop lo*lo).

#define BATCH 64
#define INF   512
#define OUTF  512
#define BASIS 8

#define NSPLIT 16
#define ISPL   (INF / NSPLIT)      // 32 i's per CTA
#define NO     64                  // o's per CTA
#define NCOL   (OUTF / NO)         // 8
#define KB     (9 * ISPL)          // 288 k per CTA
#define NK16   (KB / 16)           // 18 k16 steps per pass

// smem pitches (bytes): 16B-aligned, bank-conflict-free ldmatrix
#define APIT 592                   // A row pitch (576B data + 16 pad)
#define BPIT 144                   // B row pitch (128B data + 16 pad)

#define SM_AHI 0
#define SM_ALO (SM_AHI + 64 * APIT)
#define SM_BHI (SM_ALO + 64 * APIT)
#define SM_BLO (SM_BHI + KB * BPIT)
#define SM_TOT (SM_BLO + KB * BPIT)    // 158720

__device__ float g_partial[NSPLIT * BATCH * OUTF];   // 2 MB
__device__ int   g_ctr[NCOL];                        // zero-init; self-resetting

// ---------------- helpers ----------------
__device__ __forceinline__ uint32_t smem_u32(const void* p) {
    uint32_t a;
    asm("{ .reg .u64 t; cvta.to.shared.u64 t, %1; cvt.u32.u64 %0, t; }" : "=r"(a) : "l"(p));
    return a;
}
__device__ __forceinline__ void hilo2(float v0, float v1, uint32_t& hi, uint32_t& lo) {
    asm("cvt.rn.bf16x2.f32 %0, %1, %2;" : "=r"(hi) : "f"(v1), "f"(v0));  // low16 = v0
    float h0 = __uint_as_float(hi << 16);
    float h1 = __uint_as_float(hi & 0xffff0000u);
    float l0 = v0 - h0, l1 = v1 - h1;
    asm("cvt.rn.bf16x2.f32 %0, %1, %2;" : "=r"(lo) : "f"(l1), "f"(l0));
}
__device__ __forceinline__ void ldmA(uint32_t* a, uint32_t addr) {
    asm volatile("ldmatrix.sync.aligned.m8n8.x4.shared.b16 {%0,%1,%2,%3}, [%4];"
                 : "=r"(a[0]), "=r"(a[1]), "=r"(a[2]), "=r"(a[3]) : "r"(addr));
}
__device__ __forceinline__ void ldmB(uint32_t* b, uint32_t addr) {
    asm volatile("ldmatrix.sync.aligned.m8n8.x2.trans.shared.b16 {%0,%1}, [%2];"
                 : "=r"(b[0]), "=r"(b[1]) : "r"(addr));
}
__device__ __forceinline__ void mma16816(float* d, const uint32_t* a, const uint32_t* b) {
    asm volatile("mma.sync.aligned.m16n8k16.row.col.f32.bf16.bf16.f32 "
                 "{%0,%1,%2,%3}, {%4,%5,%6,%7}, {%8,%9}, {%0,%1,%2,%3};"
                 : "+f"(d[0]), "+f"(d[1]), "+f"(d[2]), "+f"(d[3])
                 : "r"(a[0]), "r"(a[1]), "r"(a[2]), "r"(a[3]), "r"(b[0]), "r"(b[1]));
}

__global__ __launch_bounds__(256, 1)
void kan_mma(const float* __restrict__ x,
             const float* __restrict__ w,
             const float* __restrict__ c,
             float* __restrict__ out) {
    extern __shared__ char sm[];
    __shared__ int s_last;

    const int tid  = threadIdx.x;
    const int wid  = tid >> 5, lane = tid & 31;
    const int o0   = blockIdx.x * NO;
    const int ks   = blockIdx.y;
    const int i0   = ks * ISPL;

    // ================= build A: basis hi/lo, [b][k] rows, k = j*32 + i =================
    // 512 tasks (b, i-quad), 256 threads -> 2 reps
#pragma unroll
    for (int r = 0; r < 2; r++) {
        const int tau = tid + r * 256;
        const int b   = tau >> 3;
        const int iq  = (tau & 7) * 4;
        float4 xv = *reinterpret_cast<const float4*>(&x[(size_t)b * INF + i0 + iq]);
        float v[4] = {xv.x, xv.y, xv.z, xv.w};
        float sil[4], t[4], tm1[4], tm2[4];
#pragma unroll
        for (int u = 0; u < 4; u++) {
            sil[u] = v[u] / (1.0f + __expf(-v[u]));
            float tt = tanhf(v[u]);
            t[u] = fminf(fmaxf(tt, -1.0f + 1e-6f), 1.0f - 1e-6f);
        }
        const int rowoff = b * APIT + iq * 2;
        auto stA = [&](int j, const float* q) {
            uint32_t h01, l01, h23, l23;
            hilo2(q[0], q[1], h01, l01);
            hilo2(q[2], q[3], h23, l23);
            const int off = rowoff + j * (ISPL * 2);
            *reinterpret_cast<uint2*>(sm + SM_AHI + off) = make_uint2(h01, h23);
            *reinterpret_cast<uint2*>(sm + SM_ALO + off) = make_uint2(l01, l23);
        };
        stA(0, sil);
        stA(1, t);
#pragma unroll
        for (int u = 0; u < 4; u++) { tm2[u] = t[u]; tm1[u] = 2.0f * t[u] * t[u] - 1.0f; }
        stA(2, tm1);
#pragma unroll
        for (int k = 3; k <= BASIS; k++) {
            float tk[4];
#pragma unroll
            for (int u = 0; u < 4; u++) {
                tk[u] = 2.0f * t[u] * tm1[u] - tm2[u];
                tm2[u] = tm1[u]; tm1[u] = tk[u];
            }
            stA(k, tk);
        }
    }

    // ================= build B: W2^T hi/lo, [k][o] rows =================
    // j=0 rows: plain w. 512 tasks -> 2 reps
#pragma unroll
    for (int r = 0; r < 2; r++) {
        const int tau = tid + r * 256;
        const int iL  = tau >> 4;
        const int oq  = (tau & 15) * 4;
        float4 wq = *reinterpret_cast<const float4*>(&w[(size_t)(i0 + iL) * OUTF + o0 + oq]);
        uint32_t h01, l01, h23, l23;
        hilo2(wq.x, wq.y, h01, l01);
        hilo2(wq.z, wq.w, h23, l23);
        const int off = iL * BPIT + oq * 2;
        *reinterpret_cast<uint2*>(sm + SM_BHI + off) = make_uint2(h01, h23);
        *reinterpret_cast<uint2*>(sm + SM_BLO + off) = make_uint2(l01, l23);
    }
    // j=1..8 rows: c*w. 1024 tasks (h, i, o-quad) -> 4 reps
#pragma unroll
    for (int r = 0; r < 4; r++) {
        const int tau = tid + r * 256;
        const int h   = tau >> 9;
        const int rem = tau & 511;
        const int iL  = rem >> 4;
        const int oq  = (rem & 15) * 4;
        float4 wq = *reinterpret_cast<const float4*>(&w[(size_t)(i0 + iL) * OUTF + o0 + oq]);
        const float* wv = &wq.x;
        float4 cq[4];
#pragma unroll
        for (int u = 0; u < 4; u++)
            cq[u] = reinterpret_cast<const float4*>(c)
                        [((size_t)(i0 + iL) * OUTF + o0 + oq + u) * 2 + h];
        const float* cf[4] = {&cq[0].x, &cq[1].x, &cq[2].x, &cq[3].x};
#pragma unroll
        for (int jj = 0; jj < 4; jj++) {
            const int j = h * 4 + jj + 1;
            float p0 = cf[0][jj] * wv[0], p1 = cf[1][jj] * wv[1];
            float p2 = cf[2][jj] * wv[2], p3 = cf[3][jj] * wv[3];
            uint32_t h01, l01, h23, l23;
            hilo2(p0, p1, h01, l01);
            hilo2(p2, p3, h23, l23);
            const int off = (j * ISPL + iL) * BPIT + oq * 2;
            *reinterpret_cast<uint2*>(sm + SM_BHI + off) = make_uint2(h01, h23);
            *reinterpret_cast<uint2*>(sm + SM_BLO + off) = make_uint2(l01, l23);
        }
    }
    __syncthreads();

    // ================= MMA mainloop: 8 warps, each 2 m-tiles x 2 n-tiles =================
    const int mgrp = wid >> 2;                   // 0..1 -> m rows mgrp*32..+31
    const int ngrp = wid & 3;                    // 0..3 -> o cols ngrp*16..+15
    const int n0   = ngrp * 16;

    const uint32_t aRow = (lane & 15), aSeg = (lane >> 4) * 16;
    const uint32_t aHiB = smem_u32(sm + SM_AHI) + (mgrp * 32 + aRow) * APIT + aSeg;
    const uint32_t aLoB = smem_u32(sm + SM_ALO) + (mgrp * 32 + aRow) * APIT + aSeg;
    const uint32_t bHiB = smem_u32(sm + SM_BHI) + (lane & 15) * BPIT + n0 * 2;
    const uint32_t bLoB = smem_u32(sm + SM_BLO) + (lane & 15) * BPIT + n0 * 2;

    float acc[2][2][4];
#pragma unroll
    for (int mt = 0; mt < 2; mt++)
#pragma unroll
        for (int nt = 0; nt < 2; nt++)
#pragma unroll
            for (int q = 0; q < 4; q++) acc[mt][nt][q] = 0.0f;

#pragma unroll
    for (int p = 0; p < 3; p++) {
        const uint32_t aB = (p < 2) ? aHiB : aLoB;     // Ah*Bh, Ah*Bl, Al*Bh
        const uint32_t bB = (p == 1) ? bLoB : bHiB;
#pragma unroll 3
        for (int s = 0; s < NK16; s++) {
            uint32_t afr[2][4];
#pragma unroll
            for (int mt = 0; mt < 2; mt++)
                ldmA(afr[mt], aB + mt * 16 * APIT + s * 32);
            uint32_t bfr[2][2];
#pragma unroll
            for (int nt = 0; nt < 2; nt++)
                ldmB(bfr[nt], bB + s * 16 * BPIT + nt * 16);
#pragma unroll
            for (int mt = 0; mt < 2; mt++)
#pragma unroll
                for (int nt = 0; nt < 2; nt++)
                    mma16816(acc[mt][nt], afr[mt], bfr[nt]);
        }
    }

    // ================= write partials =================
    float* pp = g_partial + (size_t)ks * (BATCH * OUTF);
#pragma unroll
    for (int mt = 0; mt < 2; mt++)
#pragma unroll
        for (int nt = 0; nt < 2; nt++) {
            const int row = mgrp * 32 + mt * 16 + (lane >> 2);
            const int col = o0 + n0 + nt * 8 + (lane & 3) * 2;
            *reinterpret_cast<float2*>(pp + (size_t)row * OUTF + col) =
                make_float2(acc[mt][nt][0], acc[mt][nt][1]);
            *reinterpret_cast<float2*>(pp + (size_t)(row + 8) * OUTF + col) =
                make_float2(acc[mt][nt][2], acc[mt][nt][3]);
        }

    // ================= fused reduce: last CTA per o-column =================
    __threadfence();
    if (tid == 0)
        s_last = (atomicAdd(&g_ctr[blockIdx.x], 1) == NSPLIT - 1) ? 1 : 0;
    __syncthreads();
    if (s_last) {
        __threadfence();
        // 64 b x 64 o = 1024 float4; 256 threads -> 4 each
#pragma unroll
        for (int rep = 0; rep < 4; rep++) {
            const int qi = tid + rep * 256;
            const int b  = qi >> 4;
            const int oq = qi & 15;
            const float* base = g_partial + (size_t)b * OUTF + o0 + oq * 4;
            float4 s = make_float4(0.f, 0.f, 0.f, 0.f);
#pragma unroll
            for (int sp = 0; sp < NSPLIT; sp++) {
                float4 v = *reinterpret_cast<const float4*>(base + (size_t)sp * (BATCH * OUTF));
                s.x += v.x; s.y += v.y; s.z += v.z; s.w += v.w;
            }
            *reinterpret_cast<float4*>(out + (size_t)b * OUTF + o0 + oq * 4) = s;
        }
        __syncthreads();
        if (tid == 0) g_ctr[blockIdx.x] = 0;           // reset for graph replay
    }
}

extern "C" void kernel_launch(void* const* d_in, const int* in_sizes, int n_in,
                              void* d_out, int out_size) {
    const float* x = (const float*)d_in[0];
    const float* w = (const float*)d_in[1];
    const float* c = (const float*)d_in[2];
    float* out = (float*)d_out;

    cudaFuncSetAttribute(kan_mma, cudaFuncAttributeMaxDynamicSharedMemorySize, SM_TOT);
    kan_mma<<<dim3(NCOL, NSPLIT), 256, SM_TOT>>>(x, w, c, out);
}